// round 13
// baseline (speedup 1.0000x reference)
#include <cuda_runtime.h>
#include <cuda_fp16.h>

#define NN   8192
#define DIM  128
#define EE   262144
#define CAP  96          // per-node bucket capacity (multiple of 8); P(deg>=96) ~ e^-41

// ---------------- scratch (static device globals — no allocation) ----------
// g_cnt relies on zero-init at module load; k_spmm2 re-zeros each row after
// its final use. Row NN of the fp16 tables is a permanent zero row used as
// the padding target, so SpMM loops run only full 8-edge chunks.
__device__ int    g_cnt[NN];
__device__ int    g_col[NN * CAP];  // neighbor v per slot (padded to 8 with NN)
__device__ float  g_s[NN];          // deg^{-1/2} (0 if deg==0)
__device__ __align__(16) __half g_xsh [(NN + 1) * DIM]; // fp16(s[v]*x[v]); row NN = 0
__device__ __align__(16) __half g_Z1sh[(NN + 1) * DIM]; // fp16(s[v]*Z1[v]); row NN = 0
__device__ float  g_Z1[NN * DIM];   // L @ x = x - A_hat x      (fp32, GEMM block 2)
__device__ float  g_V [NN * DIM];   // s_u * sum(s_v Z1_v) = A_hat Z1 (GEMM block 3)

// ---------------- build: one pass, fixed-slot buckets ----------------------
__global__ void k_fill(const int* __restrict__ ei) {
    int e = blockIdx.x * blockDim.x + threadIdx.x;
    if (e < EE) {
        int u = ei[e] & (NN - 1);          // defensive mask; indices in [0,NN)
        int v = ei[EE + e] & (NN - 1);
        int pos = atomicAdd(&g_cnt[u], 1);
        if (pos < CAP) g_col[u * CAP + pos] = v;   // clamp: no OOB ever
    }
}

// Each thread handles 8 floats of one row (16 threads/row). One thread per row
// also writes s = rsqrt(deg) and pads the column list to a multiple of 8 with
// the zero-row index NN.
__global__ void k_prep(const float* __restrict__ x) {
    int i = blockIdx.x * blockDim.x + threadIdx.x;   // NN*DIM/8 threads
    int row = i >> 4;
    int d = min(__ldg(&g_cnt[row]), CAP);
    float s = (d > 0) ? rsqrtf((float)d) : 0.0f;
    if ((i & 15) == 0) {
        g_s[row] = s;
        int npad = (d + 7) & ~7;
        for (int p = d; p < npad; p++) g_col[row * CAP + p] = NN;
    }
    float4 a = __ldg((const float4*)&x[i * 8]);
    float4 b = __ldg((const float4*)&x[i * 8 + 4]);
    __half2 h0 = __float22half2_rn(make_float2(s * a.x, s * a.y));
    __half2 h1 = __float22half2_rn(make_float2(s * a.z, s * a.w));
    __half2 h2 = __float22half2_rn(make_float2(s * b.x, s * b.y));
    __half2 h3 = __float22half2_rn(make_float2(s * b.z, s * b.w));
    uint4 o;
    o.x = *reinterpret_cast<unsigned*>(&h0);
    o.y = *reinterpret_cast<unsigned*>(&h1);
    o.z = *reinterpret_cast<unsigned*>(&h2);
    o.w = *reinterpret_cast<unsigned*>(&h3);
    *(uint4*)&g_xsh[i * 8] = o;
}

// ---------------- SpMM: 2 warps per row, fp16 chunk-tree reduction ---------
__device__ __forceinline__ __half2 as_h2(unsigned u) {
    return *reinterpret_cast<__half2*>(&u);
}

// 8 independent 8B gathers; 3-level HADD2 tree inside the chunk (safe: the
// result is scaled by s~0.18 in the epilogue), single widen, 4 fp32 adds.
__device__ __forceinline__ void gather8(float4& acc, const __half* __restrict__ X,
                                        int4 ca, int4 cb, int c4) {
    uint2 u0 = __ldg((const uint2*)(X + (ca.x << 7) + c4));
    uint2 u1 = __ldg((const uint2*)(X + (ca.y << 7) + c4));
    uint2 u2 = __ldg((const uint2*)(X + (ca.z << 7) + c4));
    uint2 u3 = __ldg((const uint2*)(X + (ca.w << 7) + c4));
    uint2 u4 = __ldg((const uint2*)(X + (cb.x << 7) + c4));
    uint2 u5 = __ldg((const uint2*)(X + (cb.y << 7) + c4));
    uint2 u6 = __ldg((const uint2*)(X + (cb.z << 7) + c4));
    uint2 u7 = __ldg((const uint2*)(X + (cb.w << 7) + c4));
    __half2 lo = __hadd2(
        __hadd2(__hadd2(as_h2(u0.x), as_h2(u1.x)), __hadd2(as_h2(u2.x), as_h2(u3.x))),
        __hadd2(__hadd2(as_h2(u4.x), as_h2(u5.x)), __hadd2(as_h2(u6.x), as_h2(u7.x))));
    __half2 hi = __hadd2(
        __hadd2(__hadd2(as_h2(u0.y), as_h2(u1.y)), __hadd2(as_h2(u2.y), as_h2(u3.y))),
        __hadd2(__hadd2(as_h2(u4.y), as_h2(u5.y)), __hadd2(as_h2(u6.y), as_h2(u7.y))));
    float2 f0 = __half22float2(lo);
    float2 f1 = __half22float2(hi);
    acc.x += f0.x; acc.y += f0.y; acc.z += f1.x; acc.w += f1.y;
}

// Padded rows: only full 8-edge chunks, half h takes chunk parity h. No tail.
__device__ __forceinline__ float4 spmm_acc_half(const __half* __restrict__ X,
                                                const int* __restrict__ cols,
                                                int nc, int lane, int h) {
    float4 acc = make_float4(0.f, 0.f, 0.f, 0.f);
    int c4 = lane * 4;
    for (int c = h; c < nc; c += 2) {
        int4 ca = __ldg((const int4*)&cols[c * 8]);
        int4 cb = __ldg((const int4*)&cols[c * 8 + 4]);
        gather8(acc, X, ca, cb, c4);
    }
    return acc;
}

__device__ __forceinline__ uint2 f4_to_h4(float4 z) {
    __half2 h0 = __float22half2_rn(make_float2(z.x, z.y));
    __half2 h1 = __float22half2_rn(make_float2(z.z, z.w));
    uint2 o;
    o.x = *reinterpret_cast<unsigned*>(&h0);
    o.y = *reinterpret_cast<unsigned*>(&h1);
    return o;
}

// Block: 256 threads = 8 warps = 4 rows x 2 half-warps.
// Z1 = x - s_u * sum(xs_h) ; also store Z1s_h = fp16(s_u * Z1) for spmm2.
__global__ __launch_bounds__(256) void k_spmm1(const float* __restrict__ x) {
    __shared__ float4 part[4][32];
    int wid  = threadIdx.x >> 5;
    int lane = threadIdx.x & 31;
    int r    = wid >> 1;
    int h    = wid & 1;
    int u    = blockIdx.x * 4 + r;
    int nc   = (min(g_cnt[u], CAP) + 7) >> 3;

    float4 acc = spmm_acc_half(g_xsh, &g_col[u * CAP], nc, lane, h);

    if (h == 1) part[r][lane] = acc;
    __syncthreads();
    if (h == 0) {
        float4 p = part[r][lane];
        float s  = g_s[u];
        int idx  = u * DIM + lane * 4;
        float4 xv = __ldg((const float4*)&x[idx]);
        float4 z;
        z.x = xv.x - s * (acc.x + p.x);
        z.y = xv.y - s * (acc.y + p.y);
        z.z = xv.z - s * (acc.z + p.z);
        z.w = xv.w - s * (acc.w + p.w);
        *(float4*)&g_Z1[idx] = z;
        float4 zs = make_float4(s * z.x, s * z.y, s * z.z, s * z.w);
        *(uint2*)&g_Z1sh[idx] = f4_to_h4(zs);
    }
}

// V = s_u * sum(Z1s_h) = A_hat Z1 (pure scaled gather); resets cnt[u].
// Z2 is never materialized: folded into the GEMM's weights.
__global__ __launch_bounds__(256) void k_spmm2() {
    __shared__ float4 part[4][32];
    int wid  = threadIdx.x >> 5;
    int lane = threadIdx.x & 31;
    int r    = wid >> 1;
    int h    = wid & 1;
    int u    = blockIdx.x * 4 + r;
    int nc   = (min(g_cnt[u], CAP) + 7) >> 3;

    float4 acc = spmm_acc_half(g_Z1sh, &g_col[u * CAP], nc, lane, h);

    if (h == 1) part[r][lane] = acc;
    __syncthreads();                     // also orders cnt read before reset
    if (h == 0) {
        if (lane == 0) g_cnt[u] = 0;     // last reader; reset for next call
        float4 p = part[r][lane];
        float  s = g_s[u];
        int idx  = u * DIM + lane * 4;
        float4 v;
        v.x = s * (acc.x + p.x);
        v.y = s * (acc.y + p.y);
        v.z = s * (acc.z + p.z);
        v.w = s * (acc.w + p.w);
        *(float4*)&g_V[idx] = v;
    }
}

// ---------------- GEMM (tf32 tensor cores, folded weights) -----------------
// out = x(W0-W2) + Z1(W1+2W2) + V(-2W2) + bias  ==  xW0 + Z1W1 + Z2W2 + bias
// BM=64, BN=128, BK=32; 256 threads = 8 warps in 4(m) x 2(n); warp tile 16x64.

__device__ __forceinline__ float to_tf32(float f) {
    unsigned u;
    asm("cvt.rna.tf32.f32 %0, %1;" : "=r"(u) : "f"(f));
    return __uint_as_float(u);
}

__device__ __forceinline__ void mma_tf32(float4& d,
                                         unsigned a0, unsigned a1,
                                         unsigned a2, unsigned a3,
                                         unsigned b0, unsigned b1) {
    asm volatile(
        "mma.sync.aligned.m16n8k8.row.col.f32.tf32.tf32.f32 "
        "{%0,%1,%2,%3}, {%4,%5,%6,%7}, {%8,%9}, {%0,%1,%2,%3};"
        : "+f"(d.x), "+f"(d.y), "+f"(d.z), "+f"(d.w)
        : "r"(a0), "r"(a1), "r"(a2), "r"(a3), "r"(b0), "r"(b1));
}

__global__ __launch_bounds__(256) void k_gemm(const float* __restrict__ x,
                                              const float* __restrict__ wts,
                                              const float* __restrict__ bias,
                                              float* __restrict__ out) {
    __shared__ float As[32][68];    // [k][m], padded
    __shared__ float Bs[32][132];   // [k][n], padded

    int t      = threadIdx.x;
    int wid    = t >> 5;
    int lane   = t & 31;
    int g      = lane >> 2;         // group 0..7
    int q      = lane & 3;          // quad-lane 0..3
    int warp_m = (wid >> 1) * 16;   // 0,16,32,48
    int warp_n = (wid & 1) * 64;    // 0,64
    int m0     = blockIdx.x * 64;

    float4 acc[8];
#pragma unroll
    for (int j = 0; j < 8; j++) acc[j] = make_float4(0.f, 0.f, 0.f, 0.f);

    for (int kt = 0; kt < 384; kt += 32) {
        const float* A = (kt < 128) ? x : (kt < 256 ? g_Z1 : g_V);
        int ko = kt & 127;

        // load A tile 64x32 (transposed into As), tf32-rounded
#pragma unroll
        for (int p = 0; p < 2; p++) {
            int row = (t >> 3) + p * 32;
            int kb  = (t & 7) * 4;
            float4 v = __ldg((const float4*)&A[(m0 + row) * DIM + ko + kb]);
            As[kb + 0][row] = to_tf32(v.x);
            As[kb + 1][row] = to_tf32(v.y);
            As[kb + 2][row] = to_tf32(v.z);
            As[kb + 3][row] = to_tf32(v.w);
        }
        // load B tile 32x128 with the W2 fold, tf32-rounded
#pragma unroll
        for (int p = 0; p < 4; p++) {
            int idx = t + p * 256;        // float4 index, 1024 total
            int kk  = idx >> 5;
            int cb  = (idx & 31) * 4;
            int rr  = kt + kk;
            float4 v = __ldg((const float4*)&wts[rr * DIM + cb]);
            if (kt < 128) {               // W0 - W2
                float4 w2 = __ldg((const float4*)&wts[(256 + (rr & 127)) * DIM + cb]);
                v.x -= w2.x; v.y -= w2.y; v.z -= w2.z; v.w -= w2.w;
            } else if (kt < 256) {        // W1 + 2*W2
                float4 w2 = __ldg((const float4*)&wts[(256 + (rr & 127)) * DIM + cb]);
                v.x += 2.0f * w2.x; v.y += 2.0f * w2.y;
                v.z += 2.0f * w2.z; v.w += 2.0f * w2.w;
            } else {                      // -2*W2
                v.x = -2.0f * v.x; v.y = -2.0f * v.y;
                v.z = -2.0f * v.z; v.w = -2.0f * v.w;
            }
            v.x = to_tf32(v.x); v.y = to_tf32(v.y);
            v.z = to_tf32(v.z); v.w = to_tf32(v.w);
            *(float4*)&Bs[kk][cb] = v;
        }
        __syncthreads();

#pragma unroll
        for (int ks = 0; ks < 4; ks++) {
            int k0 = ks * 8;
            unsigned a0 = __float_as_uint(As[k0 + q    ][warp_m + g    ]);
            unsigned a1 = __float_as_uint(As[k0 + q    ][warp_m + g + 8]);
            unsigned a2 = __float_as_uint(As[k0 + q + 4][warp_m + g    ]);
            unsigned a3 = __float_as_uint(As[k0 + q + 4][warp_m + g + 8]);
#pragma unroll
            for (int j = 0; j < 8; j++) {
                int n0 = warp_n + j * 8;
                unsigned b0 = __float_as_uint(Bs[k0 + q    ][n0 + g]);
                unsigned b1 = __float_as_uint(Bs[k0 + q + 4][n0 + g]);
                mma_tf32(acc[j], a0, a1, a2, a3, b0, b1);
            }
        }
        __syncthreads();
    }

    // epilogue: c0,c1 at row g, cols 2q,2q+1 ; c2,c3 at row g+8
    int r0 = m0 + warp_m + g;
#pragma unroll
    for (int j = 0; j < 8; j++) {
        int c = warp_n + j * 8 + 2 * q;
        float b0 = __ldg(&bias[c]);
        float b1 = __ldg(&bias[c + 1]);
        out[r0 * DIM + c]           = acc[j].x + b0;
        out[r0 * DIM + c + 1]       = acc[j].y + b1;
        out[(r0 + 8) * DIM + c]     = acc[j].z + b0;
        out[(r0 + 8) * DIM + c + 1] = acc[j].w + b1;
    }
}

// ---------------- launcher --------------------------------------------------
extern "C" void kernel_launch(void* const* d_in, const int* in_sizes, int n_in,
                              void* d_out, int out_size) {
    const float* x    = (const float*)d_in[0];
    const int*   ei   = (const int*)d_in[1];      // int32 (JAX x64 disabled)
    const float* wts  = (const float*)d_in[2];
    const float* bias = (const float*)d_in[3];
    float*       out  = (float*)d_out;

    k_fill<<<EE / 256, 256>>>(ei);
    k_prep<<<NN * DIM / 8 / 256, 256>>>(x);
    k_spmm1<<<NN / 4, 256>>>(x);
    k_spmm2<<<NN / 4, 256>>>();
    k_gemm<<<NN / 64, 256>>>(x, wts, bias, out);
}

// round 14
// speedup vs baseline: 1.1569x; 1.1569x over previous
#include <cuda_runtime.h>
#include <cuda_fp16.h>

#define NN   8192
#define DIM  128
#define EE   262144
#define CAP  96          // per-node bucket capacity (multiple of 8); P(deg>=96) ~ e^-41

// ---------------- scratch (static device globals — no allocation) ----------
// g_cnt relies on zero-init at module load; k_spmm2 re-zeros each row after
// its final use. Row NN of the fp16 tables is a permanent zero row used as
// the padding target, so SpMM loops run only full 8-edge chunks.
__device__ int    g_cnt[NN];
__device__ int    g_col[NN * CAP];  // neighbor v per slot (padded to 8 with NN)
__device__ float  g_s[NN];          // deg^{-1/2} (0 if deg==0)
__device__ __align__(16) __half g_xsh [(NN + 1) * DIM]; // fp16(s[v]*x[v]); row NN = 0
__device__ __align__(16) __half g_Z1sh[(NN + 1) * DIM]; // fp16(s[v]*Z1[v]); row NN = 0
__device__ float  g_Z1[NN * DIM];   // L @ x = x - A_hat x   (fp32, for GEMM)
__device__ float  g_Z2[NN * DIM];   // T2 @ x = 2 L Z1 - x   (fp32, for GEMM)

// ---------------- build: one pass, fixed-slot buckets ----------------------
__global__ void k_fill(const int* __restrict__ ei) {
    int e = blockIdx.x * blockDim.x + threadIdx.x;
    if (e < EE) {
        int u = ei[e] & (NN - 1);          // defensive mask; indices in [0,NN)
        int v = ei[EE + e] & (NN - 1);
        int pos = atomicAdd(&g_cnt[u], 1);
        if (pos < CAP) g_col[u * CAP + pos] = v;   // clamp: no OOB ever
    }
}

// Each thread handles 8 floats of one row (16 threads/row). One thread per row
// also writes s = rsqrt(deg) and pads the column list to a multiple of 8 with
// the zero-row index NN.
__global__ void k_prep(const float* __restrict__ x) {
    int i = blockIdx.x * blockDim.x + threadIdx.x;   // NN*DIM/8 threads
    int row = i >> 4;
    int d = min(__ldg(&g_cnt[row]), CAP);
    float s = (d > 0) ? rsqrtf((float)d) : 0.0f;
    if ((i & 15) == 0) {
        g_s[row] = s;
        int npad = (d + 7) & ~7;
        for (int p = d; p < npad; p++) g_col[row * CAP + p] = NN;
    }
    float4 a = __ldg((const float4*)&x[i * 8]);
    float4 b = __ldg((const float4*)&x[i * 8 + 4]);
    __half2 h0 = __float22half2_rn(make_float2(s * a.x, s * a.y));
    __half2 h1 = __float22half2_rn(make_float2(s * a.z, s * a.w));
    __half2 h2 = __float22half2_rn(make_float2(s * b.x, s * b.y));
    __half2 h3 = __float22half2_rn(make_float2(s * b.z, s * b.w));
    uint4 o;
    o.x = *reinterpret_cast<unsigned*>(&h0);
    o.y = *reinterpret_cast<unsigned*>(&h1);
    o.z = *reinterpret_cast<unsigned*>(&h2);
    o.w = *reinterpret_cast<unsigned*>(&h3);
    *(uint4*)&g_xsh[i * 8] = o;
}

// ---------------- SpMM: 2 warps per row, fp16 chunk-tree reduction ---------
__device__ __forceinline__ __half2 as_h2(unsigned u) {
    return *reinterpret_cast<__half2*>(&u);
}

// 8 independent 8B gathers; 3-level HADD2 tree inside the chunk (safe: the
// result is scaled by s~0.18 in the epilogue), single widen, 4 fp32 adds.
__device__ __forceinline__ void gather8(float4& acc, const __half* __restrict__ X,
                                        int4 ca, int4 cb, int c4) {
    uint2 u0 = __ldg((const uint2*)(X + (ca.x << 7) + c4));
    uint2 u1 = __ldg((const uint2*)(X + (ca.y << 7) + c4));
    uint2 u2 = __ldg((const uint2*)(X + (ca.z << 7) + c4));
    uint2 u3 = __ldg((const uint2*)(X + (ca.w << 7) + c4));
    uint2 u4 = __ldg((const uint2*)(X + (cb.x << 7) + c4));
    uint2 u5 = __ldg((const uint2*)(X + (cb.y << 7) + c4));
    uint2 u6 = __ldg((const uint2*)(X + (cb.z << 7) + c4));
    uint2 u7 = __ldg((const uint2*)(X + (cb.w << 7) + c4));
    __half2 lo = __hadd2(
        __hadd2(__hadd2(as_h2(u0.x), as_h2(u1.x)), __hadd2(as_h2(u2.x), as_h2(u3.x))),
        __hadd2(__hadd2(as_h2(u4.x), as_h2(u5.x)), __hadd2(as_h2(u6.x), as_h2(u7.x))));
    __half2 hi = __hadd2(
        __hadd2(__hadd2(as_h2(u0.y), as_h2(u1.y)), __hadd2(as_h2(u2.y), as_h2(u3.y))),
        __hadd2(__hadd2(as_h2(u4.y), as_h2(u5.y)), __hadd2(as_h2(u6.y), as_h2(u7.y))));
    float2 f0 = __half22float2(lo);
    float2 f1 = __half22float2(hi);
    acc.x += f0.x; acc.y += f0.y; acc.z += f1.x; acc.w += f1.y;
}

// Padded rows: only full 8-edge chunks, half h takes chunk parity h. No tail.
__device__ __forceinline__ float4 spmm_acc_half(const __half* __restrict__ X,
                                                const int* __restrict__ cols,
                                                int nc, int lane, int h) {
    float4 acc = make_float4(0.f, 0.f, 0.f, 0.f);
    int c4 = lane * 4;
    for (int c = h; c < nc; c += 2) {
        int4 ca = __ldg((const int4*)&cols[c * 8]);
        int4 cb = __ldg((const int4*)&cols[c * 8 + 4]);
        gather8(acc, X, ca, cb, c4);
    }
    return acc;
}

__device__ __forceinline__ uint2 f4_to_h4(float4 z) {
    __half2 h0 = __float22half2_rn(make_float2(z.x, z.y));
    __half2 h1 = __float22half2_rn(make_float2(z.z, z.w));
    uint2 o;
    o.x = *reinterpret_cast<unsigned*>(&h0);
    o.y = *reinterpret_cast<unsigned*>(&h1);
    return o;
}

// Block: 256 threads = 8 warps = 4 rows x 2 half-warps.
// Z1 = x - s_u * sum(xs_h) ; also store Z1s_h = fp16(s_u * Z1) for spmm2.
__global__ __launch_bounds__(256) void k_spmm1(const float* __restrict__ x) {
    __shared__ float4 part[4][32];
    int wid  = threadIdx.x >> 5;
    int lane = threadIdx.x & 31;
    int r    = wid >> 1;
    int h    = wid & 1;
    int u    = blockIdx.x * 4 + r;
    int nc   = (min(g_cnt[u], CAP) + 7) >> 3;

    float4 acc = spmm_acc_half(g_xsh, &g_col[u * CAP], nc, lane, h);

    if (h == 1) part[r][lane] = acc;
    __syncthreads();
    if (h == 0) {
        float4 p = part[r][lane];
        float s  = g_s[u];
        int idx  = u * DIM + lane * 4;
        float4 xv = __ldg((const float4*)&x[idx]);
        float4 z;
        z.x = xv.x - s * (acc.x + p.x);
        z.y = xv.y - s * (acc.y + p.y);
        z.z = xv.z - s * (acc.z + p.z);
        z.w = xv.w - s * (acc.w + p.w);
        *(float4*)&g_Z1[idx] = z;
        float4 zs = make_float4(s * z.x, s * z.y, s * z.z, s * z.w);
        *(uint2*)&g_Z1sh[idx] = f4_to_h4(zs);
    }
}

// Z2 = 2*Z1 - 2*s_u*sum(Z1s_h) - x ; also resets cnt[u] for replay
__global__ __launch_bounds__(256) void k_spmm2(const float* __restrict__ x) {
    __shared__ float4 part[4][32];
    int wid  = threadIdx.x >> 5;
    int lane = threadIdx.x & 31;
    int r    = wid >> 1;
    int h    = wid & 1;
    int u    = blockIdx.x * 4 + r;
    int nc   = (min(g_cnt[u], CAP) + 7) >> 3;

    float4 acc = spmm_acc_half(g_Z1sh, &g_col[u * CAP], nc, lane, h);

    if (h == 1) part[r][lane] = acc;
    __syncthreads();                     // also orders cnt read before reset
    if (h == 0) {
        if (lane == 0) g_cnt[u] = 0;     // last reader; reset for next call
        float4 p  = part[r][lane];
        float  s2 = 2.0f * g_s[u];
        int idx   = u * DIM + lane * 4;
        float4 xv = __ldg((const float4*)&x[idx]);
        float4 z1 = __ldg((const float4*)&g_Z1[idx]);
        float4 z;
        z.x = 2.0f * z1.x - s2 * (acc.x + p.x) - xv.x;
        z.y = 2.0f * z1.y - s2 * (acc.y + p.y) - xv.y;
        z.z = 2.0f * z1.z - s2 * (acc.z + p.z) - xv.z;
        z.w = 2.0f * z1.w - s2 * (acc.w + p.w) - xv.w;
        *(float4*)&g_Z2[idx] = z;
    }
}

// ---------------- GEMM (tf32 tensor cores) ---------------------------------
// out = [x|Z1|Z2](8192x384) @ W(384x128) + bias
// BM=64, BN=128, BK=32; 256 threads = 8 warps in 4(m) x 2(n); warp tile 16x64.

__device__ __forceinline__ float to_tf32(float f) {
    unsigned u;
    asm("cvt.rna.tf32.f32 %0, %1;" : "=r"(u) : "f"(f));
    return __uint_as_float(u);
}

__device__ __forceinline__ void mma_tf32(float4& d,
                                         unsigned a0, unsigned a1,
                                         unsigned a2, unsigned a3,
                                         unsigned b0, unsigned b1) {
    asm volatile(
        "mma.sync.aligned.m16n8k8.row.col.f32.tf32.tf32.f32 "
        "{%0,%1,%2,%3}, {%4,%5,%6,%7}, {%8,%9}, {%0,%1,%2,%3};"
        : "+f"(d.x), "+f"(d.y), "+f"(d.z), "+f"(d.w)
        : "r"(a0), "r"(a1), "r"(a2), "r"(a3), "r"(b0), "r"(b1));
}

__global__ __launch_bounds__(256) void k_gemm(const float* __restrict__ x,
                                              const float* __restrict__ wts,
                                              const float* __restrict__ bias,
                                              float* __restrict__ out) {
    __shared__ float As[32][68];    // [k][m], padded
    __shared__ float Bs[32][132];   // [k][n], padded

    int t      = threadIdx.x;
    int wid    = t >> 5;
    int lane   = t & 31;
    int g      = lane >> 2;         // group 0..7
    int q      = lane & 3;          // quad-lane 0..3
    int warp_m = (wid >> 1) * 16;   // 0,16,32,48
    int warp_n = (wid & 1) * 64;    // 0,64
    int m0     = blockIdx.x * 64;

    float4 acc[8];
#pragma unroll
    for (int j = 0; j < 8; j++) acc[j] = make_float4(0.f, 0.f, 0.f, 0.f);

    for (int kt = 0; kt < 384; kt += 32) {
        const float* A = (kt < 128) ? x : (kt < 256 ? g_Z1 : g_Z2);
        int ko = kt & 127;

        // load A tile 64x32 (transposed into As), tf32-rounded
#pragma unroll
        for (int p = 0; p < 2; p++) {
            int row = (t >> 3) + p * 32;
            int kb  = (t & 7) * 4;
            float4 v = __ldg((const float4*)&A[(m0 + row) * DIM + ko + kb]);
            As[kb + 0][row] = to_tf32(v.x);
            As[kb + 1][row] = to_tf32(v.y);
            As[kb + 2][row] = to_tf32(v.z);
            As[kb + 3][row] = to_tf32(v.w);
        }
        // load B tile 32x128, tf32-rounded
#pragma unroll
        for (int p = 0; p < 4; p++) {
            int idx = t + p * 256;        // float4 index, 1024 total
            int kk  = idx >> 5;
            int cb  = (idx & 31) * 4;
            float4 v = __ldg((const float4*)&wts[(kt + kk) * DIM + cb]);
            v.x = to_tf32(v.x); v.y = to_tf32(v.y);
            v.z = to_tf32(v.z); v.w = to_tf32(v.w);
            *(float4*)&Bs[kk][cb] = v;
        }
        __syncthreads();

#pragma unroll
        for (int ks = 0; ks < 4; ks++) {
            int k0 = ks * 8;
            unsigned a0 = __float_as_uint(As[k0 + q    ][warp_m + g    ]);
            unsigned a1 = __float_as_uint(As[k0 + q    ][warp_m + g + 8]);
            unsigned a2 = __float_as_uint(As[k0 + q + 4][warp_m + g    ]);
            unsigned a3 = __float_as_uint(As[k0 + q + 4][warp_m + g + 8]);
#pragma unroll
            for (int j = 0; j < 8; j++) {
                int n0 = warp_n + j * 8;
                unsigned b0 = __float_as_uint(Bs[k0 + q    ][n0 + g]);
                unsigned b1 = __float_as_uint(Bs[k0 + q + 4][n0 + g]);
                mma_tf32(acc[j], a0, a1, a2, a3, b0, b1);
            }
        }
        __syncthreads();
    }

    // epilogue: c0,c1 at row g, cols 2q,2q+1 ; c2,c3 at row g+8
    int r0 = m0 + warp_m + g;
#pragma unroll
    for (int j = 0; j < 8; j++) {
        int c = warp_n + j * 8 + 2 * q;
        float b0 = __ldg(&bias[c]);
        float b1 = __ldg(&bias[c + 1]);
        out[r0 * DIM + c]           = acc[j].x + b0;
        out[r0 * DIM + c + 1]       = acc[j].y + b1;
        out[(r0 + 8) * DIM + c]     = acc[j].z + b0;
        out[(r0 + 8) * DIM + c + 1] = acc[j].w + b1;
    }
}

// ---------------- launcher --------------------------------------------------
extern "C" void kernel_launch(void* const* d_in, const int* in_sizes, int n_in,
                              void* d_out, int out_size) {
    const float* x    = (const float*)d_in[0];
    const int*   ei   = (const int*)d_in[1];      // int32 (JAX x64 disabled)
    const float* wts  = (const float*)d_in[2];
    const float* bias = (const float*)d_in[3];
    float*       out  = (float*)d_out;

    k_fill<<<EE / 256, 256>>>(ei);
    k_prep<<<NN * DIM / 8 / 256, 256>>>(x);
    k_spmm1<<<NN / 4, 256>>>(x);
    k_spmm2<<<NN / 4, 256>>>(x);
    k_gemm<<<NN / 64, 256>>>(x, wts, bias, out);
}